// round 15
// baseline (speedup 1.0000x reference)
#include <cuda_runtime.h>
#include <cuda_bf16.h>
#include <math.h>
#include <stdint.h>

#define BB 4
#define SS 2048
#define DD 1024
#define HH 16
#define HDIM 64
#define MR (BB*SS)          // 8192 rows

typedef unsigned short ushortt;

// Scratch (allocation-free: device globals). All bf16 hi/lo split pairs.
__device__ ushortt g_xh[(size_t)MR*DD],  g_xl[(size_t)MR*DD];          // x
__device__ ushortt g_wqh[(size_t)DD*3*DD], g_wql[(size_t)DD*3*DD];     // W_qkv
__device__ ushortt g_woh[(size_t)DD*DD], g_wol[(size_t)DD*DD];         // W_out
__device__ ushortt g_qh[(size_t)BB*HH*SS*HDIM], g_ql[(size_t)BB*HH*SS*HDIM];
__device__ ushortt g_kh[(size_t)BB*HH*SS*HDIM], g_kl[(size_t)BB*HH*SS*HDIM];
__device__ ushortt g_vh[(size_t)BB*HH*SS*HDIM], g_vl[(size_t)BB*HH*SS*HDIM];
__device__ ushortt g_attnh[(size_t)MR*DD], g_attnl[(size_t)MR*DD];

// ---------------------------------------------------------------------------
// helpers (baseline PTX ISA only: plain sm_103 target)
// ---------------------------------------------------------------------------
__device__ __forceinline__ uint32_t smem_u32(const void* p) {
    uint32_t a;
    asm("{ .reg .u64 t; cvta.to.shared.u64 t, %1; cvt.u32.u64 %0, t; }"
        : "=r"(a) : "l"(p));
    return a;
}
__device__ __forceinline__ void ldsm4(uint32_t addr, uint32_t r[4]) {
    asm volatile("ldmatrix.sync.aligned.m8n8.x4.shared.b16 {%0,%1,%2,%3}, [%4];"
                 : "=r"(r[0]), "=r"(r[1]), "=r"(r[2]), "=r"(r[3]) : "r"(addr) : "memory");
}
__device__ __forceinline__ void ldsm4t(uint32_t addr, uint32_t r[4]) {
    asm volatile("ldmatrix.sync.aligned.m8n8.x4.trans.shared.b16 {%0,%1,%2,%3}, [%4];"
                 : "=r"(r[0]), "=r"(r[1]), "=r"(r[2]), "=r"(r[3]) : "r"(addr) : "memory");
}
__device__ __forceinline__ void mma16816(float d[4], const uint32_t a[4],
                                         uint32_t b0, uint32_t b1) {
    asm volatile(
        "mma.sync.aligned.m16n8k16.row.col.f32.bf16.bf16.f32 "
        "{%0,%1,%2,%3}, {%4,%5,%6,%7}, {%8,%9}, {%0,%1,%2,%3};"
        : "+f"(d[0]), "+f"(d[1]), "+f"(d[2]), "+f"(d[3])
        : "r"(a[0]), "r"(a[1]), "r"(a[2]), "r"(a[3]), "r"(b0), "r"(b1));
}
__device__ __forceinline__ void split2(float x, float y, uint32_t& h, uint32_t& l) {
    __nv_bfloat16 hx = __float2bfloat16(x), hy = __float2bfloat16(y);
    float rx = x - __bfloat162float(hx);
    float ry = y - __bfloat162float(hy);
    __nv_bfloat16 lx = __float2bfloat16(rx), ly = __float2bfloat16(ry);
    h = (uint32_t)__bfloat16_as_ushort(hx) | ((uint32_t)__bfloat16_as_ushort(hy) << 16);
    l = (uint32_t)__bfloat16_as_ushort(lx) | ((uint32_t)__bfloat16_as_ushort(ly) << 16);
}
__device__ __forceinline__ void cp_async16(uint32_t dst, const void* src) {
    asm volatile("cp.async.cg.shared.global [%0], [%1], 16;" :: "r"(dst), "l"(src));
}
__device__ __forceinline__ void cp_commit() {
    asm volatile("cp.async.commit_group;" ::: "memory");
}
__device__ __forceinline__ void cp_wait0() {
    asm volatile("cp.async.wait_group 0;" ::: "memory");
}

// ---------------------------------------------------------------------------
// HMMA GEMM, bf16 inputs, cp.async 2-stage pipeline, 512 threads.
// CTA 128x128, BK=64 (16 chunks). 16 warps, warp tile 32x32 (4x4 warp grid).
// MODE 0: A=g_xh/l, W=g_wqh/l (N=3072), scatter bf16 q/k/v (q *0.125).
// MODE 1: A=g_attnh/l, W=g_woh/l (N=1024), fp32 out + bias.
// ---------------------------------------------------------------------------
#define A_RS 144              // 64 bf16 = 128B + 16 pad
#define W_RS 272              // 128 bf16 = 256B + 16 pad
#define GA_H 0
#define GA_L 18432
#define GW_H 36864
#define GW_L 54272
#define STAGE_SZ 71680
#define GEMM_SMEM (2*STAGE_SZ)   // 143360

template<int MODE>
__global__ __launch_bounds__(512, 1) void mma_gemm(const float* __restrict__ bias,
                                                   float* __restrict__ C, int N) {
    extern __shared__ char sm[];
    const ushortt* Ah = (MODE == 0) ? g_xh : g_attnh;
    const ushortt* Al = (MODE == 0) ? g_xl : g_attnl;
    const ushortt* Wh = (MODE == 0) ? g_wqh : g_woh;
    const ushortt* Wl = (MODE == 0) ? g_wql : g_wol;

    const int tid = threadIdx.x;
    const int warp = tid >> 5, lane = tid & 31;
    const int wm = (warp >> 2) * 32;        // 4 warp-rows
    const int wn = (warp & 3) * 32;         // 4 warp-cols
    const int n0 = blockIdx.x * 128;
    const int m0 = blockIdx.y * 128;
    const uint32_t smb = smem_u32(sm);

    const int sel = lane >> 3, rr = lane & 7;
    const uint32_t aOff = (uint32_t)(((sel & 1) * 8 + rr) * A_RS + (sel >> 1) * 16);
    const uint32_t bOff = (uint32_t)(((sel & 1) * 8 + rr) * W_RS + (sel >> 1) * 16);

    // prefetch one chunk into stage st (512 threads)
#define GEMM_PREFETCH(st, c) do {                                          \
        uint32_t base_ = smb + (st) * STAGE_SZ;                            \
        int k0_ = (c) * 64;                                                \
        _Pragma("unroll")                                                  \
        for (int i_ = 0; i_ < 2; i_++) {                                   \
            int t_ = tid + i_ * 512;                                       \
            int row_ = t_ >> 3, cg_ = t_ & 7;                              \
            size_t g_ = (size_t)(m0 + row_) * DD + k0_ + cg_ * 8;          \
            uint32_t d_ = base_ + row_ * A_RS + cg_ * 16;                  \
            cp_async16(d_ + GA_H, Ah + g_);                                \
            cp_async16(d_ + GA_L, Al + g_);                                \
        }                                                                  \
        _Pragma("unroll")                                                  \
        for (int i_ = 0; i_ < 2; i_++) {                                   \
            int t_ = tid + i_ * 512;                                       \
            int row_ = t_ >> 4, cg_ = t_ & 15;                             \
            size_t g_ = (size_t)(k0_ + row_) * N + n0 + cg_ * 8;           \
            uint32_t d_ = base_ + row_ * W_RS + cg_ * 16;                  \
            cp_async16(d_ + GW_H, Wh + g_);                                \
            cp_async16(d_ + GW_L, Wl + g_);                                \
        }                                                                  \
    } while (0)

    float acc[2][4][4];
#pragma unroll
    for (int mi = 0; mi < 2; mi++)
#pragma unroll
        for (int ni = 0; ni < 4; ni++)
#pragma unroll
            for (int j = 0; j < 4; j++) acc[mi][ni][j] = 0.f;

    GEMM_PREFETCH(0, 0);
    cp_commit();

    for (int c = 0; c < 16; c++) {
        cp_wait0();
        __syncthreads();
        if (c + 1 < 16) {
            GEMM_PREFETCH((c + 1) & 1, c + 1);
            cp_commit();
        }
        const uint32_t sb = smb + (c & 1) * STAGE_SZ;

#pragma unroll
        for (int ks = 0; ks < 4; ks++) {
            uint32_t ah[2][4], al[2][4], bh[2][4], bl[2][4];
#pragma unroll
            for (int mi = 0; mi < 2; mi++) {
                uint32_t ad = aOff + (uint32_t)((wm + mi * 16) * A_RS + ks * 32);
                ldsm4(sb + GA_H + ad, ah[mi]);
                ldsm4(sb + GA_L + ad, al[mi]);
            }
#pragma unroll
            for (int ng = 0; ng < 2; ng++) {
                uint32_t bd = bOff + (uint32_t)(ks * 16 * W_RS + (wn + ng * 16) * 2);
                ldsm4t(sb + GW_H + bd, bh[ng]);
                ldsm4t(sb + GW_L + bd, bl[ng]);
            }
#pragma unroll
            for (int mi = 0; mi < 2; mi++)
#pragma unroll
                for (int ng = 0; ng < 2; ng++) {
                    mma16816(acc[mi][2*ng],   ah[mi], bh[ng][0], bh[ng][1]);
                    mma16816(acc[mi][2*ng],   ah[mi], bl[ng][0], bl[ng][1]);
                    mma16816(acc[mi][2*ng],   al[mi], bh[ng][0], bh[ng][1]);
                    mma16816(acc[mi][2*ng+1], ah[mi], bh[ng][2], bh[ng][3]);
                    mma16816(acc[mi][2*ng+1], ah[mi], bl[ng][2], bl[ng][3]);
                    mma16816(acc[mi][2*ng+1], al[mi], bh[ng][2], bh[ng][3]);
                }
        }
        __syncthreads();   // all warps done reading this stage before c+2 overwrites
    }

    // ---- Epilogue
    const int gid = lane >> 2, tig = lane & 3;
#pragma unroll
    for (int mi = 0; mi < 2; mi++) {
        int r0 = m0 + wm + mi * 16 + gid;
#pragma unroll
        for (int ni = 0; ni < 4; ni++) {
            int col = n0 + wn + ni * 8 + tig * 2;
            float bv0 = bias[col], bv1 = bias[col + 1];
            float v00 = acc[mi][ni][0] + bv0, v01 = acc[mi][ni][1] + bv1;
            float v10 = acc[mi][ni][2] + bv0, v11 = acc[mi][ni][3] + bv1;
            if (MODE == 0) {
                const int part = n0 >> 10;
                const int dcol = col & 1023;
                const int h = dcol >> 6, hd = dcol & 63;
                ushortt* bh_ = (part == 0) ? g_qh : (part == 1) ? g_kh : g_vh;
                ushortt* bl_ = (part == 0) ? g_ql : (part == 1) ? g_kl : g_vl;
                if (part == 0) { v00 *= 0.125f; v01 *= 0.125f; v10 *= 0.125f; v11 *= 0.125f; }
                int b0_ = r0 >> 11, s0_ = r0 & 2047;
                int r1 = r0 + 8;
                int b1_ = r1 >> 11, s1_ = r1 & 2047;
                size_t o0 = ((size_t)(b0_ * HH + h) * SS + s0_) * HDIM + hd;
                size_t o1 = ((size_t)(b1_ * HH + h) * SS + s1_) * HDIM + hd;
                uint32_t ph, pl;
                split2(v00, v01, ph, pl);
                *(uint32_t*)(bh_ + o0) = ph;  *(uint32_t*)(bl_ + o0) = pl;
                split2(v10, v11, ph, pl);
                *(uint32_t*)(bh_ + o1) = ph;  *(uint32_t*)(bl_ + o1) = pl;
            } else {
                *(float2*)(C + (size_t)r0 * DD + col)       = make_float2(v00, v01);
                *(float2*)(C + (size_t)(r0 + 8) * DD + col) = make_float2(v10, v11);
            }
        }
    }
}

// ---------------------------------------------------------------------------
// HMMA flash attention, bf16 pre-split inputs, cp.async KV double buffer.
// (unchanged from round 8, passing)
// ---------------------------------------------------------------------------
#define K_RS 144
#define ATT_STAGE 36864
#define ATT_SMEM (2*ATT_STAGE)    // 73728

__global__ __launch_bounds__(256) void attn_mma() {
    extern __shared__ char sm[];
    const int tid = threadIdx.x;
    const int warp = tid >> 5, lane = tid & 31;
    const int qt = blockIdx.x, bh = blockIdx.y;
    const int m0 = qt * 128;
    const int gid = lane >> 2, tig = lane & 3;
    const int sel = lane >> 3, rr = lane & 7;
    const uint32_t frOff = (uint32_t)(((sel & 1) * 8 + rr) * K_RS + (sel >> 1) * 16);
    const uint32_t smb = smem_u32(sm);

    const size_t hb = (size_t)bh * SS * HDIM;
    const ushortt* Qh = g_qh + hb;  const ushortt* Ql = g_ql + hb;
    const ushortt* Kh = g_kh + hb;  const ushortt* Kl = g_kl + hb;
    const ushortt* Vh = g_vh + hb;  const ushortt* Vl = g_vl + hb;

#define ATT_PREFETCH(st, j) do {                                            \
        uint32_t base_ = smb + (st) * ATT_STAGE;                            \
        _Pragma("unroll")                                                   \
        for (int i_ = 0; i_ < 2; i_++) {                                    \
            int t_ = tid + i_ * 256;                                        \
            int row_ = t_ >> 3, cg_ = t_ & 7;                               \
            size_t g_ = (size_t)((j) * 64 + row_) * HDIM + cg_ * 8;         \
            uint32_t d_ = base_ + row_ * K_RS + cg_ * 16;                   \
            cp_async16(d_,         Kh + g_);                                \
            cp_async16(d_ + 9216,  Kl + g_);                                \
            cp_async16(d_ + 18432, Vh + g_);                                \
            cp_async16(d_ + 27648, Vl + g_);                                \
        }                                                                   \
    } while (0)

    ATT_PREFETCH(0, 0);
    cp_commit();

    // ---- stage Q (bf16) into stage-1 region, extract A-frags
#pragma unroll
    for (int i = 0; i < 4; i++) {
        int t = tid + i * 256;
        int row = t >> 3, cg = t & 7;
        size_t g = (size_t)(m0 + row) * HDIM + cg * 8;
        uint32_t d = smb + ATT_STAGE + row * K_RS + cg * 16;
        *(uint4*)(sm + (d - smb))         = *(const uint4*)(Qh + g);
        *(uint4*)(sm + (d - smb) + 18432) = *(const uint4*)(Ql + g);
    }
    __syncthreads();
    uint32_t qh[4][4], ql[4][4];
#pragma unroll
    for (int ks = 0; ks < 4; ks++) {
        uint32_t ad = smb + ATT_STAGE + frOff + (uint32_t)(warp * 16 * K_RS + ks * 32);
        ldsm4(ad, qh[ks]);
        ldsm4(ad + 18432, ql[ks]);
    }
    __syncthreads();

    float mrow[2] = {-INFINITY, -INFINITY};
    float lrow[2] = {0.f, 0.f};
    float o[8][4];
#pragma unroll
    for (int ng = 0; ng < 8; ng++)
#pragma unroll
        for (int e = 0; e < 4; e++) o[ng][e] = 0.f;

    const int r_lo = m0 + warp * 16 + gid;
    const int r_hi = r_lo + 8;
    const int jmax = 2 * qt + 1;

    for (int j = 0; j <= jmax; j++) {
        cp_wait0();
        __syncthreads();
        if (j < jmax) {
            ATT_PREFETCH((j + 1) & 1, j + 1);
            cp_commit();
        }
        const uint32_t sb = smb + (j & 1) * ATT_STAGE;

        float s[8][4];
#pragma unroll
        for (int ng = 0; ng < 8; ng++)
#pragma unroll
            for (int e = 0; e < 4; e++) s[ng][e] = 0.f;
#pragma unroll
        for (int ks = 0; ks < 4; ks++) {
#pragma unroll
            for (int kg = 0; kg < 4; kg++) {
                uint32_t kd = sb + frOff + (uint32_t)(kg * 16 * K_RS + ks * 32);
                uint32_t kh4[4], kl4[4];
                ldsm4(kd, kh4);
                ldsm4(kd + 9216, kl4);
                mma16816(s[2*kg],   qh[ks], kh4[0], kh4[2]);
                mma16816(s[2*kg],   qh[ks], kl4[0], kl4[2]);
                mma16816(s[2*kg],   ql[ks], kh4[0], kh4[2]);
                mma16816(s[2*kg+1], qh[ks], kh4[1], kh4[3]);
                mma16816(s[2*kg+1], qh[ks], kl4[1], kl4[3]);
                mma16816(s[2*kg+1], ql[ks], kh4[1], kh4[3]);
            }
        }

        if (j >= 2 * qt) {
#pragma unroll
            for (int ng = 0; ng < 8; ng++) {
                int cg = j * 64 + ng * 8 + tig * 2;
                if (cg     > r_lo) s[ng][0] = -INFINITY;
                if (cg + 1 > r_lo) s[ng][1] = -INFINITY;
                if (cg     > r_hi) s[ng][2] = -INFINITY;
                if (cg + 1 > r_hi) s[ng][3] = -INFINITY;
            }
        }

        float mt0 = -INFINITY, mt1 = -INFINITY;
#pragma unroll
        for (int ng = 0; ng < 8; ng++) {
            mt0 = fmaxf(mt0, fmaxf(s[ng][0], s[ng][1]));
            mt1 = fmaxf(mt1, fmaxf(s[ng][2], s[ng][3]));
        }
        mt0 = fmaxf(mt0, __shfl_xor_sync(0xffffffffu, mt0, 1));
        mt0 = fmaxf(mt0, __shfl_xor_sync(0xffffffffu, mt0, 2));
        mt1 = fmaxf(mt1, __shfl_xor_sync(0xffffffffu, mt1, 1));
        mt1 = fmaxf(mt1, __shfl_xor_sync(0xffffffffu, mt1, 2));
        float mn0 = fmaxf(mrow[0], mt0), mn1 = fmaxf(mrow[1], mt1);
        float a0 = __expf(mrow[0] - mn0), a1 = __expf(mrow[1] - mn1);
        float rs0 = 0.f, rs1 = 0.f;
#pragma unroll
        for (int ng = 0; ng < 8; ng++) {
            s[ng][0] = __expf(s[ng][0] - mn0);
            s[ng][1] = __expf(s[ng][1] - mn0);
            s[ng][2] = __expf(s[ng][2] - mn1);
            s[ng][3] = __expf(s[ng][3] - mn1);
            rs0 += s[ng][0] + s[ng][1];
            rs1 += s[ng][2] + s[ng][3];
        }
        rs0 += __shfl_xor_sync(0xffffffffu, rs0, 1);
        rs0 += __shfl_xor_sync(0xffffffffu, rs0, 2);
        rs1 += __shfl_xor_sync(0xffffffffu, rs1, 1);
        rs1 += __shfl_xor_sync(0xffffffffu, rs1, 2);
        lrow[0] = lrow[0] * a0 + rs0;
        lrow[1] = lrow[1] * a1 + rs1;
        mrow[0] = mn0; mrow[1] = mn1;
#pragma unroll
        for (int ng = 0; ng < 8; ng++) {
            o[ng][0] *= a0; o[ng][1] *= a0;
            o[ng][2] *= a1; o[ng][3] *= a1;
        }

#pragma unroll
        for (int kc = 0; kc < 4; kc++) {
            uint32_t pha[4], pla[4];
            split2(s[2*kc][0],   s[2*kc][1],   pha[0], pla[0]);
            split2(s[2*kc][2],   s[2*kc][3],   pha[1], pla[1]);
            split2(s[2*kc+1][0], s[2*kc+1][1], pha[2], pla[2]);
            split2(s[2*kc+1][2], s[2*kc+1][3], pha[3], pla[3]);
#pragma unroll
            for (int hg = 0; hg < 4; hg++) {
                uint32_t vd = sb + frOff + (uint32_t)(kc * 16 * K_RS + hg * 32);
                uint32_t vh4[4], vl4[4];
                ldsm4t(vd + 18432, vh4);
                ldsm4t(vd + 27648, vl4);
                mma16816(o[2*hg],   pha, vh4[0], vh4[1]);
                mma16816(o[2*hg],   pha, vl4[0], vl4[1]);
                mma16816(o[2*hg],   pla, vh4[0], vh4[1]);
                mma16816(o[2*hg+1], pha, vh4[2], vh4[3]);
                mma16816(o[2*hg+1], pha, vl4[2], vl4[3]);
                mma16816(o[2*hg+1], pla, vh4[2], vh4[3]);
            }
        }
        __syncthreads();
    }

    const float inv0 = 1.f / lrow[0], inv1 = 1.f / lrow[1];
    const int b_ = bh >> 4, h = bh & 15;
#pragma unroll
    for (int ng = 0; ng < 8; ng++) {
        int col = h * 64 + ng * 8 + tig * 2;
        size_t o0 = ((size_t)(b_ * SS + r_lo)) * DD + col;
        size_t o1 = ((size_t)(b_ * SS + r_hi)) * DD + col;
        uint32_t ph, pl;
        split2(o[ng][0] * inv0, o[ng][1] * inv0, ph, pl);
        *(uint32_t*)(g_attnh + o0) = ph;  *(uint32_t*)(g_attnl + o0) = pl;
        split2(o[ng][2] * inv1, o[ng][3] * inv1, ph, pl);
        *(uint32_t*)(g_attnh + o1) = ph;  *(uint32_t*)(g_attnl + o1) = pl;
    }
}

// ---------------------------------------------------------------------------
// cvt launcher shims (bind __device__ symbols in device code)
// ---------------------------------------------------------------------------
__global__ void cvt_x_kernel(const float* __restrict__ src, int n4) {
    int i = blockIdx.x * blockDim.x + threadIdx.x;
    if (i < n4) {
        float4 v = ((const float4*)src)[i];
        uint32_t h0, l0, h1, l1;
        split2(v.x, v.y, h0, l0); split2(v.z, v.w, h1, l1);
        ((uint2*)g_xh)[i] = make_uint2(h0, h1);
        ((uint2*)g_xl)[i] = make_uint2(l0, l1);
    }
}
__global__ void cvt_wq_kernel(const float* __restrict__ src, int n4) {
    int i = blockIdx.x * blockDim.x + threadIdx.x;
    if (i < n4) {
        float4 v = ((const float4*)src)[i];
        uint32_t h0, l0, h1, l1;
        split2(v.x, v.y, h0, l0); split2(v.z, v.w, h1, l1);
        ((uint2*)g_wqh)[i] = make_uint2(h0, h1);
        ((uint2*)g_wql)[i] = make_uint2(l0, l1);
    }
}
__global__ void cvt_wo_kernel(const float* __restrict__ src, int n4) {
    int i = blockIdx.x * blockDim.x + threadIdx.x;
    if (i < n4) {
        float4 v = ((const float4*)src)[i];
        uint32_t h0, l0, h1, l1;
        split2(v.x, v.y, h0, l0); split2(v.z, v.w, h1, l1);
        ((uint2*)g_woh)[i] = make_uint2(h0, h1);
        ((uint2*)g_wol)[i] = make_uint2(l0, l1);
    }
}

// ---------------------------------------------------------------------------
extern "C" void kernel_launch(void* const* d_in, const int* in_sizes, int n_in,
                              void* d_out, int out_size) {
    const float* x     = (const float*)d_in[0];
    const float* W_qkv = (const float*)d_in[1];
    const float* b_qkv = (const float*)d_in[2];
    const float* W_out = (const float*)d_in[3];
    const float* b_out = (const float*)d_in[4];
    float* out = (float*)d_out;

    cudaFuncSetAttribute(mma_gemm<0>, cudaFuncAttributeMaxDynamicSharedMemorySize, GEMM_SMEM);
    cudaFuncSetAttribute(mma_gemm<1>, cudaFuncAttributeMaxDynamicSharedMemorySize, GEMM_SMEM);
    cudaFuncSetAttribute(attn_mma,    cudaFuncAttributeMaxDynamicSharedMemorySize, ATT_SMEM);

    {
        int n4 = MR * DD / 4;
        cvt_x_kernel<<<(n4 + 255) / 256, 256>>>(x, n4);
    }
    {
        int n4 = DD * 3 * DD / 4;
        cvt_wq_kernel<<<(n4 + 255) / 256, 256>>>(W_qkv, n4);
    }
    {
        int n4 = DD * DD / 4;
        cvt_wo_kernel<<<(n4 + 255) / 256, 256>>>(W_out, n4);
    }

    mma_gemm<0><<<dim3(3 * DD / 128, MR / 128), 512, GEMM_SMEM>>>(b_qkv, nullptr, 3 * DD);

    attn_mma<<<dim3(SS / 128, BB * HH), 256, ATT_SMEM>>>();

    mma_gemm<1><<<dim3(DD / 128, MR / 128), 512, GEMM_SMEM>>>(b_out, out, DD);
}